// round 13
// baseline (speedup 1.0000x reference)
#include <cuda_runtime.h>
#include <cuda_fp16.h>
#include <cstdint>

// ---------------------------------------------------------------------------
// SVACrossAttentionLayer on GB300.  R12: warp-per-row LN kernels, ILP'd weight
// convert, and attention bias table precomputed + cp.async-streamed (mask /
// ktid / typed-bias math removed from the attention hot loop).  GEMMs and
// attention MMA/softmax identical to R11 (both at/near their floors).
// B=2, Nq=1024, Nk=4096, HID=1024, H=16, hd=64.
// ---------------------------------------------------------------------------

#define B_       2
#define NQ       1024
#define NK       4096
#define HID      1024
#define HEADS    16
#define HD       64
#define LN_EPS   1e-5f
#define NEG_BIG  (-1e30f)
#define M_INIT   (-1e9f)

// ------------------------- scratch (static, no allocs) ---------------------
__device__ float  g_proj[B_ * NQ * HID];
__device__ float  g_bias[B_ * (NK/128) * 3 * 128];   // [b][tile][t][128]
__device__ __half g_qn  [B_ * NQ * HID];
__device__ __half g_kvn [B_ * NK * HID];
__device__ __half g_q   [B_ * NQ * HID];
__device__ __half g_k   [B_ * NK * HID];
__device__ __half g_v   [B_ * NK * HID];
__device__ __half g_att [B_ * NQ * HID];
__device__ __half g_w   [4 * HID * HID];   // Wq,Wk,Wv,Wo (fp16)

// ------------------------- PTX helpers --------------------------------------
__device__ __forceinline__ void mma_f16(
    float& c0, float& c1, float& c2, float& c3,
    uint32_t a0, uint32_t a1, uint32_t a2, uint32_t a3,
    uint32_t b0, uint32_t b1) {
    asm volatile(
        "mma.sync.aligned.m16n8k16.row.col.f32.f16.f16.f32 "
        "{%0,%1,%2,%3}, {%4,%5,%6,%7}, {%8,%9}, {%0,%1,%2,%3};"
        : "+f"(c0), "+f"(c1), "+f"(c2), "+f"(c3)
        : "r"(a0), "r"(a1), "r"(a2), "r"(a3), "r"(b0), "r"(b1));
}
__device__ __forceinline__ void ldsm_x4_trans(
    uint32_t& r0, uint32_t& r1, uint32_t& r2, uint32_t& r3, uint32_t addr) {
    asm volatile("ldmatrix.sync.aligned.m8n8.x4.trans.shared.b16 {%0,%1,%2,%3}, [%4];"
                 : "=r"(r0), "=r"(r1), "=r"(r2), "=r"(r3) : "r"(addr));
}
__device__ __forceinline__ uint32_t smem_u32(const void* p) {
    uint32_t a;
    asm("{ .reg .u64 t; cvta.to.shared.u64 t, %1; cvt.u32.u64 %0, t; }"
        : "=r"(a) : "l"(p));
    return a;
}
__device__ __forceinline__ void cpa16(uint32_t dst, const void* src) {
    asm volatile("cp.async.cg.shared.global [%0], [%1], 16;" :: "r"(dst), "l"(src));
}
#define CP_COMMIT() asm volatile("cp.async.commit_group;" ::: "memory")
#define CP_WAIT0()  asm volatile("cp.async.wait_group 0;" ::: "memory")
#define CP_WAIT1()  asm volatile("cp.async.wait_group 1;" ::: "memory")

__device__ __forceinline__ uint32_t pack_f16x2(float a, float b) {
    __half2 h = __floats2half2_rn(a, b);
    return *(uint32_t*)&h;
}
__device__ __forceinline__ void store_h2(__half* p, size_t off, float a, float b) {
    *(__half2*)&p[off] = __floats2half2_rn(a, b);
}
__device__ __forceinline__ void store_h4(__half* p, size_t off,
                                         float a, float b, float c, float d) {
    __half2 h01 = __floats2half2_rn(a, b);
    __half2 h23 = __floats2half2_rn(c, d);
    uint2 u = make_uint2(*(uint32_t*)&h01, *(uint32_t*)&h23);
    *(uint2*)&p[off] = u;
}

// ------------------------- LayerNorm -> fp16 (warp per row) -----------------
__global__ void __launch_bounds__(256) ln_cvt_kernel(
    const float* __restrict__ x, __half* __restrict__ y,
    const float* __restrict__ w, const float* __restrict__ b) {
    int warp = threadIdx.x >> 5, lane = threadIdx.x & 31;
    int row = blockIdx.x * 8 + warp;
    const float4* xr = (const float4*)(x + (size_t)row * HID);
    float4 v[8];
    float s = 0.f, ss = 0.f;
    #pragma unroll
    for (int i = 0; i < 8; ++i) {
        v[i] = xr[i*32 + lane];
        s  += v[i].x + v[i].y + v[i].z + v[i].w;
        ss += v[i].x*v[i].x + v[i].y*v[i].y + v[i].z*v[i].z + v[i].w*v[i].w;
    }
    #pragma unroll
    for (int o = 16; o; o >>= 1) {
        s  += __shfl_xor_sync(0xffffffffu, s,  o);
        ss += __shfl_xor_sync(0xffffffffu, ss, o);
    }
    float mean = s * (1.0f / HID);
    float var  = ss * (1.0f / HID) - mean * mean;
    float rstd = rsqrtf(var + LN_EPS);
    #pragma unroll
    for (int i = 0; i < 8; ++i) {
        float4 wv = ((const float4*)w)[i*32 + lane];
        float4 bv = ((const float4*)b)[i*32 + lane];
        store_h4(y, (size_t)row * HID + (i*32 + lane)*4,
                 (v[i].x - mean) * rstd * wv.x + bv.x,
                 (v[i].y - mean) * rstd * wv.y + bv.y,
                 (v[i].z - mean) * rstd * wv.z + bv.z,
                 (v[i].w - mean) * rstd * wv.w + bv.w);
    }
}

// ------------------------- fused weights -> fp16 (4 float4 / thread) --------
__global__ void __launch_bounds__(256) cvt_w_kernel(
    const float* __restrict__ W0, const float* __restrict__ W1,
    const float* __restrict__ W2, const float* __restrict__ W3,
    __half* __restrict__ y) {
    int i0 = (blockIdx.x * 256 + threadIdx.x) * 4;   // float4 index base
    #pragma unroll
    for (int j = 0; j < 4; ++j) {
        int i = i0 + j;                               // 0 .. 4*2^18-1
        int wsel = i >> 18;
        int jj = i & 0x3FFFF;
        const float* src = wsel == 0 ? W0 : wsel == 1 ? W1 : wsel == 2 ? W2 : W3;
        float4 v = ((const float4*)src)[jj];
        store_h4(y, (size_t)i * 4, v.x, v.y, v.z, v.w);
    }
}

// ------------------------- bias table precompute ----------------------------
// bias[b][tile][t][128] = tbias[t][ktid[j]] + (mask[b][j] ? 0 : NEG_BIG)
__global__ void __launch_bounds__(256) bias_kernel(
    const int* __restrict__ ktid, const int* __restrict__ mask,
    const float* __restrict__ tbias, float* __restrict__ bias) {
    int j = blockIdx.x * 256 + threadIdx.x;           // 0 .. B_*NK-1
    int b = j >> 12, k = j & (NK - 1);
    int kt = ktid[k];
    float cb = mask[j] ? 0.f : NEG_BIG;
    int tile = k >> 7, jj = k & 127;
    float* dst = bias + ((size_t)(b * (NK/128) + tile) * 3) * 128 + jj;
    dst[0*128] = tbias[0*3 + kt] + cb;
    dst[1*128] = tbias[1*3 + kt] + cb;
    dst[2*128] = tbias[2*3 + kt] + cb;
}

// ------------------------- residual + LayerNorm (warp per row) --------------
__global__ void __launch_bounds__(256) addln_kernel(
    const float* __restrict__ xq, const float* __restrict__ xp,
    float* __restrict__ y,
    const float* __restrict__ w, const float* __restrict__ b) {
    int warp = threadIdx.x >> 5, lane = threadIdx.x & 31;
    int row = blockIdx.x * 8 + warp;
    const float4* qr = (const float4*)(xq + (size_t)row * HID);
    const float4* pr = (const float4*)(xp + (size_t)row * HID);
    float4 v[8];
    float s = 0.f, ss = 0.f;
    #pragma unroll
    for (int i = 0; i < 8; ++i) {
        float4 a = qr[i*32 + lane], c = pr[i*32 + lane];
        v[i].x = a.x + c.x; v[i].y = a.y + c.y;
        v[i].z = a.z + c.z; v[i].w = a.w + c.w;
        s  += v[i].x + v[i].y + v[i].z + v[i].w;
        ss += v[i].x*v[i].x + v[i].y*v[i].y + v[i].z*v[i].z + v[i].w*v[i].w;
    }
    #pragma unroll
    for (int o = 16; o; o >>= 1) {
        s  += __shfl_xor_sync(0xffffffffu, s,  o);
        ss += __shfl_xor_sync(0xffffffffu, ss, o);
    }
    float mean = s * (1.0f / HID);
    float var  = ss * (1.0f / HID) - mean * mean;
    float rstd = rsqrtf(var + LN_EPS);
    #pragma unroll
    for (int i = 0; i < 8; ++i) {
        float4 wv = ((const float4*)w)[i*32 + lane];
        float4 bv = ((const float4*)b)[i*32 + lane];
        float4 o;
        o.x = (v[i].x - mean) * rstd * wv.x + bv.x;
        o.y = (v[i].y - mean) * rstd * wv.y + bv.y;
        o.z = (v[i].z - mean) * rstd * wv.z + bv.z;
        o.w = (v[i].w - mean) * rstd * wv.w + bv.w;
        ((float4*)(y + (size_t)row * HID))[i*32 + lane] = o;
    }
}

// ------------------------- HMMA GEMM (fp16, cp.async double-buffered) -------
#define GPAD 72
#define TILE_H   (128 * GPAD)
#define TILE_B   (TILE_H * 2)
#define GEMM_SMEM (4 * TILE_B)

#define GEMM_LOAD(ktv, buf)                                                   \
    do {                                                                      \
        _Pragma("unroll")                                                     \
        for (int l = 0; l < 4; ++l) {                                         \
            int idx = tid + l * 256;                                          \
            int row = idx >> 3, c = idx & 7;                                  \
            size_t ga = (size_t)(m0 + row) * HID + (ktv) * 64 + c * 8;        \
            size_t gw = (size_t)(n0 + row) * HID + (ktv) * 64 + c * 8;        \
            uint32_t ds = (uint32_t)(row * GPAD + c * 8) * 2;                 \
            cpa16(smb + (buf) * 2 * TILE_B + ds,          &A[ga]);            \
            cpa16(smb + (buf) * 2 * TILE_B + TILE_B + ds, &W[gw]);            \
        }                                                                     \
        CP_COMMIT();                                                          \
    } while (0)

#define GEMM_BODY(EPILOGUE)                                                   \
    extern __shared__ __half smem[];                                          \
    uint32_t smb = smem_u32(smem);                                            \
    int tid = threadIdx.x, wid = tid >> 5, lane = tid & 31;                   \
    int group = lane >> 2, tig = lane & 3;                                    \
    int m0 = blockIdx.y * 128, n0 = blockIdx.x * 128;                         \
    int wm = (wid >> 2) * 64, wn = (wid & 3) * 32;                            \
    float acc[4][4][4] = {};                                                  \
    GEMM_LOAD(0, 0);                                                          \
    for (int kt = 0; kt < 16; ++kt) {                                         \
        if (kt < 15) GEMM_LOAD(kt + 1, (kt + 1) & 1);                         \
        if (kt < 15) { CP_WAIT1(); } else { CP_WAIT0(); }                     \
        __syncthreads();                                                      \
        __half* sA = smem + (kt & 1) * 2 * TILE_H;                            \
        __half* sW = sA + TILE_H;                                             \
        _Pragma("unroll")                                                     \
        for (int ks = 0; ks < 4; ++ks) {                                      \
            int kb = ks * 16;                                                 \
            uint32_t af[4][4];                                                \
            _Pragma("unroll")                                                 \
            for (int mi = 0; mi < 4; ++mi) {                                  \
                int r0 = wm + mi * 16 + group;                                \
                int o00 = r0 * GPAD + kb + tig * 2;                           \
                int o10 = (r0 + 8) * GPAD + kb + tig * 2;                     \
                af[mi][0] = *(uint32_t*)&sA[o00];                             \
                af[mi][1] = *(uint32_t*)&sA[o10];                             \
                af[mi][2] = *(uint32_t*)&sA[o00 + 8];                         \
                af[mi][3] = *(uint32_t*)&sA[o10 + 8];                         \
            }                                                                 \
            _Pragma("unroll")                                                 \
            for (int ni = 0; ni < 4; ++ni) {                                  \
                int nr = wn + ni * 8 + group;                                 \
                int ob = nr * GPAD + kb + tig * 2;                            \
                uint32_t b0 = *(uint32_t*)&sW[ob];                            \
                uint32_t b1 = *(uint32_t*)&sW[ob + 8];                        \
                _Pragma("unroll")                                             \
                for (int mi = 0; mi < 4; ++mi)                                \
                    mma_f16(acc[mi][ni][0], acc[mi][ni][1],                   \
                            acc[mi][ni][2], acc[mi][ni][3],                   \
                            af[mi][0], af[mi][1], af[mi][2], af[mi][3],       \
                            b0, b1);                                          \
            }                                                                 \
        }                                                                     \
        __syncthreads();                                                      \
    }                                                                         \
    EPILOGUE

__global__ void __launch_bounds__(256, 2) hmma_gemm_h(
    const __half* __restrict__ A, const __half* __restrict__ W,
    __half* __restrict__ C) {
    GEMM_BODY(
        _Pragma("unroll")
        for (int mi = 0; mi < 4; ++mi) {
            int r0 = m0 + wm + mi * 16 + group;
            _Pragma("unroll")
            for (int ni = 0; ni < 4; ++ni) {
                int cc = n0 + wn + ni * 8 + tig * 2;
                store_h2(C, (size_t)r0 * HID + cc,       acc[mi][ni][0], acc[mi][ni][1]);
                store_h2(C, (size_t)(r0 + 8) * HID + cc, acc[mi][ni][2], acc[mi][ni][3]);
            }
        }
    )
}

__global__ void __launch_bounds__(256, 2) hmma_gemm_f(
    const __half* __restrict__ A, const __half* __restrict__ W,
    float* __restrict__ C) {
    GEMM_BODY(
        _Pragma("unroll")
        for (int mi = 0; mi < 4; ++mi) {
            int r0 = m0 + wm + mi * 16 + group;
            _Pragma("unroll")
            for (int ni = 0; ni < 4; ++ni) {
                int cc = n0 + wn + ni * 8 + tig * 2;
                *(float2*)&C[(size_t)r0 * HID + cc] =
                    make_float2(acc[mi][ni][0], acc[mi][ni][1]);
                *(float2*)&C[(size_t)(r0 + 8) * HID + cc] =
                    make_float2(acc[mi][ni][2], acc[mi][ni][3]);
            }
        }
    )
}

// ------------------------- pipelined fp16 flash attention --------------------
// 8 warps, 128 q-rows per block.  K double-buffered, V single-buffered.
// Bias table streamed via cp.async (same group as V).
#define APAD 72
#define SQ_  (128 * APAD)
#define ATT_SMEM_BYTES (4 * SQ_ * 2 + 3*128*4 + 64)

__global__ void __launch_bounds__(256) attn_hmma(
    const __half* __restrict__ Qg, const __half* __restrict__ Kg,
    const __half* __restrict__ Vg,
    const int* __restrict__ qtid,
    const float* __restrict__ biasg,
    __half* __restrict__ O) {
    extern __shared__ __half sm[];
    __half* sQ = sm;                 // K0 at 1*SQ_, K1 at 2*SQ_, V at 3*SQ_
    float* sB  = (float*)((char*)sm + 4 * SQ_ * 2);   // [3][128]
    uint32_t smb = smem_u32(sm);
    uint32_t sbB = smb + 4 * SQ_ * 2;

    int tid = threadIdx.x, w = tid >> 5, lane = tid & 31;
    int group = lane >> 2, tig = lane & 3;
    int b = blockIdx.z, h = blockIdx.y, q0 = blockIdx.x * 128;

    // ---- preload Q and K(0) via cp.async ----
    #pragma unroll
    for (int t = 0; t < 4; ++t) {
        int idx = tid + t * 256;
        int row = idx >> 3, ch = idx & 7;
        size_t gq = (size_t)(b*NQ + q0 + row) * HID + h*HD + ch*8;
        cpa16(smb + (row * APAD + ch * 8) * 2, Qg + gq);
    }
    CP_COMMIT();
    #pragma unroll
    for (int t = 0; t < 4; ++t) {
        int idx = tid + t * 256;
        int row = idx >> 3, ch = idx & 7;
        size_t gk = (size_t)(b*NK + row) * HID + h*HD + ch*8;
        cpa16(smb + SQ_*2 + (row * APAD + ch * 8) * 2, Kg + gk);
    }
    CP_COMMIT();
    CP_WAIT0();
    __syncthreads();

    int qt0 = qtid[q0 + w*16 + group];
    int qt1 = qtid[q0 + w*16 + group + 8];

    float m0 = M_INIT, m1 = M_INIT, l0 = 0.f, l1 = 0.f;
    float oacc[8][4] = {};
    int cur = 0;
    int ldm_m = lane >> 3, ldm_r = lane & 7;

    for (int kt = 0; kt < 32; ++kt) {
        int kv0 = kt * 128;
        // V(kt) + bias(kt) copies (one commit group)
        #pragma unroll
        for (int t = 0; t < 4; ++t) {
            int idx = tid + t * 256;
            int row = idx >> 3, ch = idx & 7;
            size_t gv = (size_t)(b*NK + kv0 + row) * HID + h*HD + ch*8;
            cpa16(smb + 3*SQ_*2 + (row * APAD + ch * 8) * 2, Vg + gv);
        }
        if (tid < 96)
            cpa16(sbB + tid * 16,
                  biasg + ((size_t)(b * (NK/128) + kt) * 3) * 128 + tid * 4);
        CP_COMMIT();
        bool pre = (kt < 31);
        if (pre) {
            int nb = cur ^ 1;
            #pragma unroll
            for (int t = 0; t < 4; ++t) {
                int idx = tid + t * 256;
                int row = idx >> 3, ch = idx & 7;
                size_t gk = (size_t)(b*NK + kv0 + 128 + row) * HID + h*HD + ch*8;
                cpa16(smb + (1 + nb)*SQ_*2 + (row * APAD + ch * 8) * 2, Kg + gk);
            }
            CP_COMMIT();
        }

        // ---- S = Q @ K^T (fp16 single) ----
        __half* sK = sm + (1 + cur) * SQ_;
        float sacc[16][4] = {};
        #pragma unroll
        for (int kc = 0; kc < 4; ++kc) {
            int ro = (w*16 + group) * APAD + kc*16 + tig*2;
            uint32_t a0 = *(uint32_t*)&sQ[ro];
            uint32_t a1 = *(uint32_t*)&sQ[ro + 8*APAD];
            uint32_t a2 = *(uint32_t*)&sQ[ro + 8];
            uint32_t a3 = *(uint32_t*)&sQ[ro + 8*APAD + 8];
            #pragma unroll
            for (int ni = 0; ni < 16; ++ni) {
                int bo = (ni*8 + group) * APAD + kc*16 + tig*2;
                uint32_t b0 = *(uint32_t*)&sK[bo];
                uint32_t b1 = *(uint32_t*)&sK[bo + 8];
                mma_f16(sacc[ni][0], sacc[ni][1], sacc[ni][2], sacc[ni][3],
                        a0, a1, a2, a3, b0, b1);
            }
        }

        // V + bias ready
        if (pre) { CP_WAIT1(); } else { CP_WAIT0(); }
        __syncthreads();

        // ---- epilogue + online softmax ----
        float mx0 = -3.0e38f, mx1 = -3.0e38f;
        const float* b0r = sB + qt0*128;
        const float* b1r = sB + qt1*128;
        #pragma unroll
        for (int ni = 0; ni < 16; ++ni) {
            int j0 = ni*8 + tig*2;
            sacc[ni][0] = sacc[ni][0] * 0.125f + b0r[j0];
            sacc[ni][1] = sacc[ni][1] * 0.125f + b0r[j0+1];
            sacc[ni][2] = sacc[ni][2] * 0.125f + b1r[j0];
            sacc[ni][3] = sacc[ni][3] * 0.125f + b1r[j0+1];
            mx0 = fmaxf(mx0, fmaxf(sacc[ni][0], sacc[ni][1]));
            mx1 = fmaxf(mx1, fmaxf(sacc[ni][2], sacc[ni][3]));
        }
        mx0 = fmaxf(mx0, __shfl_xor_sync(0xffffffffu, mx0, 1));
        mx0 = fmaxf(mx0, __shfl_xor_sync(0xffffffffu, mx0, 2));
        mx1 = fmaxf(mx1, __shfl_xor_sync(0xffffffffu, mx1, 1));
        mx1 = fmaxf(mx1, __shfl_xor_sync(0xffffffffu, mx1, 2));
        float mn0 = fmaxf(m0, mx0), mn1 = fmaxf(m1, mx1);
        float al_0 = __expf(m0 - mn0), al_1 = __expf(m1 - mn1);
        m0 = mn0; m1 = mn1;
        float sum0 = 0.f, sum1 = 0.f;
        #pragma unroll
        for (int ni = 0; ni < 16; ++ni) {
            float p0 = __expf(sacc[ni][0] - mn0);
            float p1 = __expf(sacc[ni][1] - mn0);
            float p2 = __expf(sacc[ni][2] - mn1);
            float p3 = __expf(sacc[ni][3] - mn1);
            sacc[ni][0] = p0; sacc[ni][1] = p1;
            sacc[ni][2] = p2; sacc[ni][3] = p3;
            sum0 += p0 + p1; sum1 += p2 + p3;
        }
        sum0 += __shfl_xor_sync(0xffffffffu, sum0, 1);
        sum0 += __shfl_xor_sync(0xffffffffu, sum0, 2);
        sum1 += __shfl_xor_sync(0xffffffffu, sum1, 1);
        sum1 += __shfl_xor_sync(0xffffffffu, sum1, 2);
        l0 = l0 * al_0 + sum0;
        l1 = l1 * al_1 + sum1;
        #pragma unroll
        for (int nd = 0; nd < 8; ++nd) {
            oacc[nd][0] *= al_0; oacc[nd][1] *= al_0;
            oacc[nd][2] *= al_1; oacc[nd][3] *= al_1;
        }

        // ---- O += P @ V via ldmatrix.x4.trans on row-major V ----
        uint32_t vb = smb + 3*SQ_*2;
        #pragma unroll
        for (int kk = 0; kk < 8; ++kk) {
            uint32_t p0 = pack_f16x2(sacc[2*kk][0],   sacc[2*kk][1]);
            uint32_t p1 = pack_f16x2(sacc[2*kk][2],   sacc[2*kk][3]);
            uint32_t p2 = pack_f16x2(sacc[2*kk+1][0], sacc[2*kk+1][1]);
            uint32_t p3 = pack_f16x2(sacc[2*kk+1][2], sacc[2*kk+1][3]);
            int rowb = kk*16 + (ldm_m & 1)*8 + ldm_r;
            #pragma unroll
            for (int ndp = 0; ndp < 4; ++ndp) {
                uint32_t off = (uint32_t)(rowb * APAD + ndp*16 + (ldm_m >> 1)*8) * 2;
                uint32_t v0, v1, v2, v3;
                ldsm_x4_trans(v0, v1, v2, v3, vb + off);
                mma_f16(oacc[2*ndp][0], oacc[2*ndp][1],
                        oacc[2*ndp][2], oacc[2*ndp][3],
                        p0, p1, p2, p3, v0, v1);
                mma_f16(oacc[2*ndp+1][0], oacc[2*ndp+1][1],
                        oacc[2*ndp+1][2], oacc[2*ndp+1][3],
                        p0, p1, p2, p3, v2, v3);
            }
        }

        CP_WAIT0();           // K(kt+1) landed
        __syncthreads();      // V free, K(kt+1) visible
        cur ^= 1;
    }

    float inv0 = 1.0f / l0, inv1 = 1.0f / l1;
    int r0g = b*NQ + q0 + w*16 + group;
    #pragma unroll
    for (int nd = 0; nd < 8; ++nd) {
        int cc = h*HD + nd*8 + tig*2;
        store_h2(O, (size_t)r0g * HID + cc,       oacc[nd][0]*inv0, oacc[nd][1]*inv0);
        store_h2(O, (size_t)(r0g + 8) * HID + cc, oacc[nd][2]*inv1, oacc[nd][3]*inv1);
    }
}

// ---------------------------------------------------------------------------
extern "C" void kernel_launch(void* const* d_in, const int* in_sizes, int n_in,
                              void* d_out, int out_size) {
    const float* queries = (const float*)d_in[0];
    const float* kv      = (const float*)d_in[1];
    const int*   qtid    = (const int*)d_in[2];
    const int*   ktid    = (const int*)d_in[3];
    const int*   mask    = (const int*)d_in[4];   // widened bool
    const float* Wq      = (const float*)d_in[5];
    const float* Wk      = (const float*)d_in[6];
    const float* Wv      = (const float*)d_in[7];
    const float* Wo      = (const float*)d_in[8];
    const float* qn_w    = (const float*)d_in[9];
    const float* qn_b    = (const float*)d_in[10];
    const float* kvn_w   = (const float*)d_in[11];
    const float* kvn_b   = (const float*)d_in[12];
    const float* on_w    = (const float*)d_in[13];
    const float* on_b    = (const float*)d_in[14];
    const float* tbias   = (const float*)d_in[15];
    float*       out     = (float*)d_out;

    float *proj, *bias;
    __half *qn, *kvn, *q, *k, *v, *att, *wgt;
    cudaGetSymbolAddress((void**)&proj, g_proj);
    cudaGetSymbolAddress((void**)&bias, g_bias);
    cudaGetSymbolAddress((void**)&qn,   g_qn);
    cudaGetSymbolAddress((void**)&kvn,  g_kvn);
    cudaGetSymbolAddress((void**)&q,    g_q);
    cudaGetSymbolAddress((void**)&k,    g_k);
    cudaGetSymbolAddress((void**)&v,    g_v);
    cudaGetSymbolAddress((void**)&att,  g_att);
    cudaGetSymbolAddress((void**)&wgt,  g_w);

    cudaFuncSetAttribute(hmma_gemm_h, cudaFuncAttributeMaxDynamicSharedMemorySize,
                         GEMM_SMEM);
    cudaFuncSetAttribute(hmma_gemm_f, cudaFuncAttributeMaxDynamicSharedMemorySize,
                         GEMM_SMEM);
    cudaFuncSetAttribute(attn_hmma, cudaFuncAttributeMaxDynamicSharedMemorySize,
                         ATT_SMEM_BYTES);

    const int WN = HID * HID;

    // 1) LayerNorm -> fp16 (warp per row) + bias table
    ln_cvt_kernel<<<B_ * NQ / 8, 256>>>(queries, qn, qn_w, qn_b);
    ln_cvt_kernel<<<B_ * NK / 8, 256>>>(kv, kvn, kvn_w, kvn_b);
    bias_kernel<<<B_ * NK / 256, 256>>>(ktid, mask, tbias, bias);

    // 2) weights -> fp16 (single launch, 4 float4 per thread)
    cvt_w_kernel<<<1024, 256>>>(Wq, Wk, Wv, Wo, wgt);

    // 3) projections (fp16, cp.async-pipelined)
    hmma_gemm_h<<<dim3(8, (B_*NQ)/128), 256, GEMM_SMEM>>>(qn,  wgt + 0*WN, q);
    hmma_gemm_h<<<dim3(8, (B_*NK)/128), 256, GEMM_SMEM>>>(kvn, wgt + 1*WN, k);
    hmma_gemm_h<<<dim3(8, (B_*NK)/128), 256, GEMM_SMEM>>>(kvn, wgt + 2*WN, v);

    // 4) attention (fp16 flash, bias streamed)
    attn_hmma<<<dim3(NQ/128, HEADS, B_), 256, ATT_SMEM_BYTES>>>(
        q, k, v, qtid, bias, att);

    // 5) out projection (fp32 output)
    hmma_gemm_f<<<dim3(8, (B_*NQ)/128), 256, GEMM_SMEM>>>(att, wgt + 3*WN, proj);

    // 6) residual + LN
    addln_kernel<<<B_ * NQ / 8, 256>>>(queries, proj, out, on_w, on_b);
}

// round 17
// speedup vs baseline: 1.0922x; 1.0922x over previous
#include <cuda_runtime.h>
#include <cuda_fp16.h>
#include <cstdint>

// ---------------------------------------------------------------------------
// SVACrossAttentionLayer on GB300.  R16 = R15 resubmitted verbatim (the GB300
// container broker failed twice before running it; no kernel signal).
// R15 = R13 launch-structure round with the QKV grid bug fixed: K and V each
// need 64 m-tiles (8192 rows), so the fused projection launch is 1152 blocks
// (128 Q + 512 K + 512 V).  Prep (2x LN-convert, weight convert, bias table)
// fused into ONE kernel.  Attention / out-proj / addln identical to R12.
// B=2, Nq=1024, Nk=4096, HID=1024, H=16, hd=64.
// ---------------------------------------------------------------------------

#define B_       2
#define NQ       1024
#define NK       4096
#define HID      1024
#define HEADS    16
#define HD       64
#define LN_EPS   1e-5f
#define NEG_BIG  (-1e30f)
#define M_INIT   (-1e9f)

// ------------------------- scratch (static, no allocs) ---------------------
__device__ float  g_proj[B_ * NQ * HID];
__device__ float  g_bias[B_ * (NK/128) * 3 * 128];   // [b][tile][t][128]
__device__ __half g_qn  [B_ * NQ * HID];
__device__ __half g_kvn [B_ * NK * HID];
__device__ __half g_q   [B_ * NQ * HID];
__device__ __half g_k   [B_ * NK * HID];
__device__ __half g_v   [B_ * NK * HID];
__device__ __half g_att [B_ * NQ * HID];
__device__ __half g_w   [4 * HID * HID];   // Wq,Wk,Wv,Wo (fp16)

// ------------------------- PTX helpers --------------------------------------
__device__ __forceinline__ void mma_f16(
    float& c0, float& c1, float& c2, float& c3,
    uint32_t a0, uint32_t a1, uint32_t a2, uint32_t a3,
    uint32_t b0, uint32_t b1) {
    asm volatile(
        "mma.sync.aligned.m16n8k16.row.col.f32.f16.f16.f32 "
        "{%0,%1,%2,%3}, {%4,%5,%6,%7}, {%8,%9}, {%0,%1,%2,%3};"
        : "+f"(c0), "+f"(c1), "+f"(c2), "+f"(c3)
        : "r"(a0), "r"(a1), "r"(a2), "r"(a3), "r"(b0), "r"(b1));
}
__device__ __forceinline__ void ldsm_x4_trans(
    uint32_t& r0, uint32_t& r1, uint32_t& r2, uint32_t& r3, uint32_t addr) {
    asm volatile("ldmatrix.sync.aligned.m8n8.x4.trans.shared.b16 {%0,%1,%2,%3}, [%4];"
                 : "=r"(r0), "=r"(r1), "=r"(r2), "=r"(r3) : "r"(addr));
}
__device__ __forceinline__ uint32_t smem_u32(const void* p) {
    uint32_t a;
    asm("{ .reg .u64 t; cvta.to.shared.u64 t, %1; cvt.u32.u64 %0, t; }"
        : "=r"(a) : "l"(p));
    return a;
}
__device__ __forceinline__ void cpa16(uint32_t dst, const void* src) {
    asm volatile("cp.async.cg.shared.global [%0], [%1], 16;" :: "r"(dst), "l"(src));
}
#define CP_COMMIT() asm volatile("cp.async.commit_group;" ::: "memory")
#define CP_WAIT0()  asm volatile("cp.async.wait_group 0;" ::: "memory")
#define CP_WAIT1()  asm volatile("cp.async.wait_group 1;" ::: "memory")

__device__ __forceinline__ uint32_t pack_f16x2(float a, float b) {
    __half2 h = __floats2half2_rn(a, b);
    return *(uint32_t*)&h;
}
__device__ __forceinline__ void store_h2(__half* p, size_t off, float a, float b) {
    *(__half2*)&p[off] = __floats2half2_rn(a, b);
}
__device__ __forceinline__ void store_h4(__half* p, size_t off,
                                         float a, float b, float c, float d) {
    __half2 h01 = __floats2half2_rn(a, b);
    __half2 h23 = __floats2half2_rn(c, d);
    uint2 u = make_uint2(*(uint32_t*)&h01, *(uint32_t*)&h23);
    *(uint2*)&p[off] = u;
}

// ------------------------- fused prep kernel --------------------------------
// blocks [0,256): LN(queries)->qn ; [256,1280): LN(kv)->kvn ;
// [1280,2304): weights->fp16 ; [2304,2336): bias table.
__device__ __forceinline__ void ln_row_body(
    const float* __restrict__ x, __half* __restrict__ y,
    const float* __restrict__ w, const float* __restrict__ b, int blk) {
    int warp = threadIdx.x >> 5, lane = threadIdx.x & 31;
    int row = blk * 8 + warp;
    const float4* xr = (const float4*)(x + (size_t)row * HID);
    float4 v[8];
    float s = 0.f, ss = 0.f;
    #pragma unroll
    for (int i = 0; i < 8; ++i) {
        v[i] = xr[i*32 + lane];
        s  += v[i].x + v[i].y + v[i].z + v[i].w;
        ss += v[i].x*v[i].x + v[i].y*v[i].y + v[i].z*v[i].z + v[i].w*v[i].w;
    }
    #pragma unroll
    for (int o = 16; o; o >>= 1) {
        s  += __shfl_xor_sync(0xffffffffu, s,  o);
        ss += __shfl_xor_sync(0xffffffffu, ss, o);
    }
    float mean = s * (1.0f / HID);
    float var  = ss * (1.0f / HID) - mean * mean;
    float rstd = rsqrtf(var + LN_EPS);
    #pragma unroll
    for (int i = 0; i < 8; ++i) {
        float4 wv = ((const float4*)w)[i*32 + lane];
        float4 bv = ((const float4*)b)[i*32 + lane];
        store_h4(y, (size_t)row * HID + (i*32 + lane)*4,
                 (v[i].x - mean) * rstd * wv.x + bv.x,
                 (v[i].y - mean) * rstd * wv.y + bv.y,
                 (v[i].z - mean) * rstd * wv.z + bv.z,
                 (v[i].w - mean) * rstd * wv.w + bv.w);
    }
}

__global__ void __launch_bounds__(256) prep_kernel(
    const float* __restrict__ queries, const float* __restrict__ kv,
    const float* __restrict__ qn_w, const float* __restrict__ qn_b,
    const float* __restrict__ kvn_w, const float* __restrict__ kvn_b,
    const float* __restrict__ W0, const float* __restrict__ W1,
    const float* __restrict__ W2, const float* __restrict__ W3,
    const int* __restrict__ ktid, const int* __restrict__ mask,
    const float* __restrict__ tbias,
    __half* __restrict__ qn, __half* __restrict__ kvn,
    __half* __restrict__ wgt, float* __restrict__ bias) {
    int bid = blockIdx.x;
    if (bid < 256) {
        ln_row_body(queries, qn, qn_w, qn_b, bid);
    } else if (bid < 1280) {
        ln_row_body(kv, kvn, kvn_w, kvn_b, bid - 256);
    } else if (bid < 2304) {
        int i0 = ((bid - 1280) * 256 + threadIdx.x) * 4;
        #pragma unroll
        for (int j = 0; j < 4; ++j) {
            int i = i0 + j;                           // 0 .. 4*2^18-1
            int wsel = i >> 18;
            int jj = i & 0x3FFFF;
            const float* src = wsel == 0 ? W0 : wsel == 1 ? W1
                             : wsel == 2 ? W2 : W3;
            float4 v = ((const float4*)src)[jj];
            store_h4(wgt, (size_t)i * 4, v.x, v.y, v.z, v.w);
        }
    } else {
        int j = (bid - 2304) * 256 + threadIdx.x;     // 0 .. B_*NK-1
        int b = j >> 12, k = j & (NK - 1);
        int kt = ktid[k];
        float cb = mask[j] ? 0.f : NEG_BIG;
        int tile = k >> 7, jj = k & 127;
        float* dst = bias + ((size_t)(b * (NK/128) + tile) * 3) * 128 + jj;
        dst[0*128] = tbias[0*3 + kt] + cb;
        dst[1*128] = tbias[1*3 + kt] + cb;
        dst[2*128] = tbias[2*3 + kt] + cb;
    }
}

// ------------------------- residual + LayerNorm (warp per row) --------------
__global__ void __launch_bounds__(256) addln_kernel(
    const float* __restrict__ xq, const float* __restrict__ xp,
    float* __restrict__ y,
    const float* __restrict__ w, const float* __restrict__ b) {
    int warp = threadIdx.x >> 5, lane = threadIdx.x & 31;
    int row = blockIdx.x * 8 + warp;
    const float4* qr = (const float4*)(xq + (size_t)row * HID);
    const float4* pr = (const float4*)(xp + (size_t)row * HID);
    float4 v[8];
    float s = 0.f, ss = 0.f;
    #pragma unroll
    for (int i = 0; i < 8; ++i) {
        float4 a = qr[i*32 + lane], c = pr[i*32 + lane];
        v[i].x = a.x + c.x; v[i].y = a.y + c.y;
        v[i].z = a.z + c.z; v[i].w = a.w + c.w;
        s  += v[i].x + v[i].y + v[i].z + v[i].w;
        ss += v[i].x*v[i].x + v[i].y*v[i].y + v[i].z*v[i].z + v[i].w*v[i].w;
    }
    #pragma unroll
    for (int o = 16; o; o >>= 1) {
        s  += __shfl_xor_sync(0xffffffffu, s,  o);
        ss += __shfl_xor_sync(0xffffffffu, ss, o);
    }
    float mean = s * (1.0f / HID);
    float var  = ss * (1.0f / HID) - mean * mean;
    float rstd = rsqrtf(var + LN_EPS);
    #pragma unroll
    for (int i = 0; i < 8; ++i) {
        float4 wv = ((const float4*)w)[i*32 + lane];
        float4 bv = ((const float4*)b)[i*32 + lane];
        float4 o;
        o.x = (v[i].x - mean) * rstd * wv.x + bv.x;
        o.y = (v[i].y - mean) * rstd * wv.y + bv.y;
        o.z = (v[i].z - mean) * rstd * wv.z + bv.z;
        o.w = (v[i].w - mean) * rstd * wv.w + bv.w;
        ((float4*)(y + (size_t)row * HID))[i*32 + lane] = o;
    }
}

// ------------------------- HMMA GEMM core -----------------------------------
#define GPAD 72
#define TILE_H   (128 * GPAD)
#define TILE_B   (TILE_H * 2)
#define GEMM_SMEM (4 * TILE_B)

#define GEMM_LOAD(ktv, buf)                                                   \
    do {                                                                      \
        _Pragma("unroll")                                                     \
        for (int l = 0; l < 4; ++l) {                                         \
            int idx = tid + l * 256;                                          \
            int row = idx >> 3, c = idx & 7;                                  \
            size_t ga = (size_t)(m0 + row) * HID + (ktv) * 64 + c * 8;        \
            size_t gw = (size_t)(n0 + row) * HID + (ktv) * 64 + c * 8;        \
            uint32_t ds = (uint32_t)(row * GPAD + c * 8) * 2;                 \
            cpa16(smb + (buf) * 2 * TILE_B + ds,          &A[ga]);            \
            cpa16(smb + (buf) * 2 * TILE_B + TILE_B + ds, &W[gw]);            \
        }                                                                     \
        CP_COMMIT();                                                          \
    } while (0)

#define GEMM_CORE                                                             \
    extern __shared__ __half smem[];                                          \
    uint32_t smb = smem_u32(smem);                                            \
    int tid = threadIdx.x, wid = tid >> 5, lane = tid & 31;                   \
    int group = lane >> 2, tig = lane & 3;                                    \
    int wm = (wid >> 2) * 64, wn = (wid & 3) * 32;                            \
    float acc[4][4][4] = {};                                                  \
    GEMM_LOAD(0, 0);                                                          \
    for (int kt = 0; kt < 16; ++kt) {                                         \
        if (kt < 15) GEMM_LOAD(kt + 1, (kt + 1) & 1);                         \
        if (kt < 15) { CP_WAIT1(); } else { CP_WAIT0(); }                     \
        __syncthreads();                                                      \
        __half* sA = smem + (kt & 1) * 2 * TILE_H;                            \
        __half* sW = sA + TILE_H;                                             \
        _Pragma("unroll")                                                     \
        for (int ks = 0; ks < 4; ++ks) {                                      \
            int kb = ks * 16;                                                 \
            uint32_t af[4][4];                                                \
            _Pragma("unroll")                                                 \
            for (int mi = 0; mi < 4; ++mi) {                                  \
                int r0 = wm + mi * 16 + group;                                \
                int o00 = r0 * GPAD + kb + tig * 2;                           \
                int o10 = (r0 + 8) * GPAD + kb + tig * 2;                     \
                af[mi][0] = *(uint32_t*)&sA[o00];                             \
                af[mi][1] = *(uint32_t*)&sA[o10];                             \
                af[mi][2] = *(uint32_t*)&sA[o00 + 8];                         \
                af[mi][3] = *(uint32_t*)&sA[o10 + 8];                         \
            }                                                                 \
            _Pragma("unroll")                                                 \
            for (int ni = 0; ni < 4; ++ni) {                                  \
                int nr = wn + ni * 8 + group;                                 \
                int ob = nr * GPAD + kb + tig * 2;                            \
                uint32_t b0 = *(uint32_t*)&sW[ob];                            \
                uint32_t b1 = *(uint32_t*)&sW[ob + 8];                        \
                _Pragma("unroll")                                             \
                for (int mi = 0; mi < 4; ++mi)                                \
                    mma_f16(acc[mi][ni][0], acc[mi][ni][1],                   \
                            acc[mi][ni][2], acc[mi][ni][3],                   \
                            af[mi][0], af[mi][1], af[mi][2], af[mi][3],       \
                            b0, b1);                                          \
            }                                                                 \
        }                                                                     \
        __syncthreads();                                                      \
    }

// Fused Q/K/V projection: 1152 blocks.
//   [0,128):    C=q, A=qn,  W=wgt+0     (16 m-tiles x 8 n-tiles, 2048 rows)
//   [128,640):  C=k, A=kvn, W=wgt+WN    (64 m-tiles x 8 n-tiles, 8192 rows)
//   [640,1152): C=v, A=kvn, W=wgt+2WN   (64 m-tiles x 8 n-tiles, 8192 rows)
__global__ void __launch_bounds__(256, 2) hmma_gemm_qkv(
    const __half* __restrict__ qn, const __half* __restrict__ kvn,
    const __half* __restrict__ wgt,
    __half* __restrict__ q, __half* __restrict__ k, __half* __restrict__ v) {
    const int WN = HID * HID;
    int bid = blockIdx.x;
    const __half *A, *W;
    __half *C;
    int sub;
    if (bid < 128)      { A = qn;  W = wgt;          C = q; sub = bid; }
    else if (bid < 640) { A = kvn; W = wgt + WN;     C = k; sub = bid - 128; }
    else                { A = kvn; W = wgt + 2*WN;   C = v; sub = bid - 640; }
    int m0 = (sub >> 3) * 128, n0 = (sub & 7) * 128;
    GEMM_CORE
    #pragma unroll
    for (int mi = 0; mi < 4; ++mi) {
        int r0 = m0 + wm + mi * 16 + group;
        #pragma unroll
        for (int ni = 0; ni < 4; ++ni) {
            int cc = n0 + wn + ni * 8 + tig * 2;
            store_h2(C, (size_t)r0 * HID + cc,       acc[mi][ni][0], acc[mi][ni][1]);
            store_h2(C, (size_t)(r0 + 8) * HID + cc, acc[mi][ni][2], acc[mi][ni][3]);
        }
    }
}

__global__ void __launch_bounds__(256, 2) hmma_gemm_f(
    const __half* __restrict__ A, const __half* __restrict__ W,
    float* __restrict__ C) {
    int m0 = blockIdx.y * 128, n0 = blockIdx.x * 128;
    GEMM_CORE
    #pragma unroll
    for (int mi = 0; mi < 4; ++mi) {
        int r0 = m0 + wm + mi * 16 + group;
        #pragma unroll
        for (int ni = 0; ni < 4; ++ni) {
            int cc = n0 + wn + ni * 8 + tig * 2;
            *(float2*)&C[(size_t)r0 * HID + cc] =
                make_float2(acc[mi][ni][0], acc[mi][ni][1]);
            *(float2*)&C[(size_t)(r0 + 8) * HID + cc] =
                make_float2(acc[mi][ni][2], acc[mi][ni][3]);
        }
    }
}

// ------------------------- pipelined fp16 flash attention --------------------
#define APAD 72
#define SQ_  (128 * APAD)
#define ATT_SMEM_BYTES (4 * SQ_ * 2 + 3*128*4 + 64)

__global__ void __launch_bounds__(256) attn_hmma(
    const __half* __restrict__ Qg, const __half* __restrict__ Kg,
    const __half* __restrict__ Vg,
    const int* __restrict__ qtid,
    const float* __restrict__ biasg,
    __half* __restrict__ O) {
    extern __shared__ __half sm[];
    __half* sQ = sm;                 // K0 at 1*SQ_, K1 at 2*SQ_, V at 3*SQ_
    float* sB  = (float*)((char*)sm + 4 * SQ_ * 2);   // [3][128]
    uint32_t smb = smem_u32(sm);
    uint32_t sbB = smb + 4 * SQ_ * 2;

    int tid = threadIdx.x, w = tid >> 5, lane = tid & 31;
    int group = lane >> 2, tig = lane & 3;
    int b = blockIdx.z, h = blockIdx.y, q0 = blockIdx.x * 128;

    #pragma unroll
    for (int t = 0; t < 4; ++t) {
        int idx = tid + t * 256;
        int row = idx >> 3, ch = idx & 7;
        size_t gq = (size_t)(b*NQ + q0 + row) * HID + h*HD + ch*8;
        cpa16(smb + (row * APAD + ch * 8) * 2, Qg + gq);
    }
    CP_COMMIT();
    #pragma unroll
    for (int t = 0; t < 4; ++t) {
        int idx = tid + t * 256;
        int row = idx >> 3, ch = idx & 7;
        size_t gk = (size_t)(b*NK + row) * HID + h*HD + ch*8;
        cpa16(smb + SQ_*2 + (row * APAD + ch * 8) * 2, Kg + gk);
    }
    CP_COMMIT();
    CP_WAIT0();
    __syncthreads();

    int qt0 = qtid[q0 + w*16 + group];
    int qt1 = qtid[q0 + w*16 + group + 8];

    float m0 = M_INIT, m1 = M_INIT, l0 = 0.f, l1 = 0.f;
    float oacc[8][4] = {};
    int cur = 0;
    int ldm_m = lane >> 3, ldm_r = lane & 7;

    for (int kt = 0; kt < 32; ++kt) {
        int kv0 = kt * 128;
        #pragma unroll
        for (int t = 0; t < 4; ++t) {
            int idx = tid + t * 256;
            int row = idx >> 3, ch = idx & 7;
            size_t gv = (size_t)(b*NK + kv0 + row) * HID + h*HD + ch*8;
            cpa16(smb + 3*SQ_*2 + (row * APAD + ch * 8) * 2, Vg + gv);
        }
        if (tid < 96)
            cpa16(sbB + tid * 16,
                  biasg + ((size_t)(b * (NK/128) + kt) * 3) * 128 + tid * 4);
        CP_COMMIT();
        bool pre = (kt < 31);
        if (pre) {
            int nb = cur ^ 1;
            #pragma unroll
            for (int t = 0; t < 4; ++t) {
                int idx = tid + t * 256;
                int row = idx >> 3, ch = idx & 7;
                size_t gk = (size_t)(b*NK + kv0 + 128 + row) * HID + h*HD + ch*8;
                cpa16(smb + (1 + nb)*SQ_*2 + (row * APAD + ch * 8) * 2, Kg + gk);
            }
            CP_COMMIT();
        }

        __half* sK = sm + (1 + cur) * SQ_;
        float sacc[16][4] = {};
        #pragma unroll
        for (int kc = 0; kc < 4; ++kc) {
            int ro = (w*16 + group) * APAD + kc*16 + tig*2;
            uint32_t a0 = *(uint32_t*)&sQ[ro];
            uint32_t a1 = *(uint32_t*)&sQ[ro + 8*APAD];
            uint32_t a2 = *(uint32_t*)&sQ[ro + 8];
            uint32_t a3 = *(uint32_t*)&sQ[ro + 8*APAD + 8];
            #pragma unroll
            for (int ni = 0; ni < 16; ++ni) {
                int bo = (ni*8 + group) * APAD + kc*16 + tig*2;
                uint32_t b0 = *(uint32_t*)&sK[bo];
                uint32_t b1 = *(uint32_t*)&sK[bo + 8];
                mma_f16(sacc[ni][0], sacc[ni][1], sacc[ni][2], sacc[ni][3],
                        a0, a1, a2, a3, b0, b1);
            }
        }

        if (pre) { CP_WAIT1(); } else { CP_WAIT0(); }
        __syncthreads();

        float mx0 = -3.0e38f, mx1 = -3.0e38f;
        const float* b0r = sB + qt0*128;
        const float* b1r = sB + qt1*128;
        #pragma unroll
        for (int ni = 0; ni < 16; ++ni) {
            int j0 = ni*8 + tig*2;
            sacc[ni][0] = sacc[ni][0] * 0.125f + b0r[j0];
            sacc[ni][1] = sacc[ni][1] * 0.125f + b0r[j0+1];
            sacc[ni][2] = sacc[ni][2] * 0.125f + b1r[j0];
            sacc[ni][3] = sacc[ni][3] * 0.125f + b1r[j0+1];
            mx0 = fmaxf(mx0, fmaxf(sacc[ni][0], sacc[ni][1]));
            mx1 = fmaxf(mx1, fmaxf(sacc[ni][2], sacc[ni][3]));
        }
        mx0 = fmaxf(mx0, __shfl_xor_sync(0xffffffffu, mx0, 1));
        mx0 = fmaxf(mx0, __shfl_xor_sync(0xffffffffu, mx0, 2));
        mx1 = fmaxf(mx1, __shfl_xor_sync(0xffffffffu, mx1, 1));
        mx1 = fmaxf(mx1, __shfl_xor_sync(0xffffffffu, mx1, 2));
        float mn0 = fmaxf(m0, mx0), mn1 = fmaxf(m1, mx1);
        float al_0 = __expf(m0 - mn0), al_1 = __expf(m1 - mn1);
        m0 = mn0; m1 = mn1;
        float sum0 = 0.f, sum1 = 0.f;
        #pragma unroll
        for (int ni = 0; ni < 16; ++ni) {
            float p0 = __expf(sacc[ni][0] - mn0);
            float p1 = __expf(sacc[ni][1] - mn0);
            float p2 = __expf(sacc[ni][2] - mn1);
            float p3 = __expf(sacc[ni][3] - mn1);
            sacc[ni][0] = p0; sacc[ni][1] = p1;
            sacc[ni][2] = p2; sacc[ni][3] = p3;
            sum0 += p0 + p1; sum1 += p2 + p3;
        }
        sum0 += __shfl_xor_sync(0xffffffffu, sum0, 1);
        sum0 += __shfl_xor_sync(0xffffffffu, sum0, 2);
        sum1 += __shfl_xor_sync(0xffffffffu, sum1, 1);
        sum1 += __shfl_xor_sync(0xffffffffu, sum1, 2);
        l0 = l0 * al_0 + sum0;
        l1 = l1 * al_1 + sum1;
        #pragma unroll
        for (int nd = 0; nd < 8; ++nd) {
            oacc[nd][0] *= al_0; oacc[nd][1] *= al_0;
            oacc[nd][2] *= al_1; oacc[nd][3] *= al_1;
        }

        uint32_t vb = smb + 3*SQ_*2;
        #pragma unroll
        for (int kk = 0; kk < 8; ++kk) {
            uint32_t p0 = pack_f16x2(sacc[2*kk][0],   sacc[2*kk][1]);
            uint32_t p1 = pack_f16x2(sacc[2*kk][2],   sacc[2*kk][3]);
            uint32_t p2 = pack_f16x2(sacc[2*kk+1][0], sacc[2*kk+1][1]);
            uint32_t p3 = pack_f16x2(sacc[2*kk+1][2], sacc[2*kk+1][3]);
            int rowb = kk*16 + (ldm_m & 1)*8 + ldm_r;
            #pragma unroll
            for (int ndp = 0; ndp < 4; ++ndp) {
                uint32_t off = (uint32_t)(rowb * APAD + ndp*16 + (ldm_m >> 1)*8) * 2;
                uint32_t v0, v1, v2, v3;
                ldsm_x4_trans(v0, v1, v2, v3, vb + off);
                mma_f16(oacc[2*ndp][0], oacc[2*ndp][1],
                        oacc[2*ndp][2], oacc[2*ndp][3],
                        p0, p1, p2, p3, v0, v1);
                mma_f16(oacc[2*ndp+1][0], oacc[2*ndp+1][1],
                        oacc[2*ndp+1][2], oacc[2*ndp+1][3],
                        p0, p1, p2, p3, v2, v3);
            }
        }

        CP_WAIT0();
        __syncthreads();
        cur ^= 1;
    }

    float inv0 = 1.0f / l0, inv1 = 1.0f / l1;
    int r0g = b*NQ + q0 + w*16 + group;
    #pragma unroll
    for (int nd = 0; nd < 8; ++nd) {
        int cc = h*HD + nd*8 + tig*2;
        store_h2(O, (size_t)r0g * HID + cc,       oacc[nd][0]*inv0, oacc[nd][1]*inv0);
        store_h2(O, (size_t)(r0g + 8) * HID + cc, oacc[nd][2]*inv1, oacc[nd][3]*inv1);
    }
}

// ---------------------------------------------------------------------------
extern "C" void kernel_launch(void* const* d_in, const int* in_sizes, int n_in,
                              void* d_out, int out_size) {
    const float* queries = (const float*)d_in[0];
    const float* kv      = (const float*)d_in[1];
    const int*   qtid    = (const int*)d_in[2];
    const int*   ktid    = (const int*)d_in[3];
    const int*   mask    = (const int*)d_in[4];   // widened bool
    const float* Wq      = (const float*)d_in[5];
    const float* Wk      = (const float*)d_in[6];
    const float* Wv      = (const float*)d_in[7];
    const float* Wo      = (const float*)d_in[8];
    const float* qn_w    = (const float*)d_in[9];
    const float* qn_b    = (const float*)d_in[10];
    const float* kvn_w   = (const float*)d_in[11];
    const float* kvn_b   = (const float*)d_in[12];
    const float* on_w    = (const float*)d_in[13];
    const float* on_b    = (const float*)d_in[14];
    const float* tbias   = (const float*)d_in[15];
    float*       out     = (float*)d_out;

    float *proj, *bias;
    __half *qn, *kvn, *q, *k, *v, *att, *wgt;
    cudaGetSymbolAddress((void**)&proj, g_proj);
    cudaGetSymbolAddress((void**)&bias, g_bias);
    cudaGetSymbolAddress((void**)&qn,   g_qn);
    cudaGetSymbolAddress((void**)&kvn,  g_kvn);
    cudaGetSymbolAddress((void**)&q,    g_q);
    cudaGetSymbolAddress((void**)&k,    g_k);
    cudaGetSymbolAddress((void**)&v,    g_v);
    cudaGetSymbolAddress((void**)&att,  g_att);
    cudaGetSymbolAddress((void**)&wgt,  g_w);

    cudaFuncSetAttribute(hmma_gemm_qkv, cudaFuncAttributeMaxDynamicSharedMemorySize,
                         GEMM_SMEM);
    cudaFuncSetAttribute(hmma_gemm_f, cudaFuncAttributeMaxDynamicSharedMemorySize,
                         GEMM_SMEM);
    cudaFuncSetAttribute(attn_hmma, cudaFuncAttributeMaxDynamicSharedMemorySize,
                         ATT_SMEM_BYTES);

    const int WN = HID * HID;

    // 1) fused prep: LN(q), LN(kv), weights->fp16, bias table  (one launch)
    prep_kernel<<<2336, 256>>>(queries, kv, qn_w, qn_b, kvn_w, kvn_b,
                               Wq, Wk, Wv, Wo, ktid, mask, tbias,
                               qn, kvn, wgt, bias);

    // 2) fused Q/K/V projections (one 1152-block launch)
    hmma_gemm_qkv<<<1152, 256, GEMM_SMEM>>>(qn, kvn, wgt, q, k, v);

    // 3) attention
    attn_hmma<<<dim3(NQ/128, HEADS, B_), 256, ATT_SMEM_BYTES>>>(
        q, k, v, qtid, bias, att);

    // 4) out projection (fp32 output)
    hmma_gemm_f<<<dim3(8, (B_*NQ)/128), 256, GEMM_SMEM>>>(att, wgt + 3*WN, proj);

    // 5) residual + LN
    addln_kernel<<<B_ * NQ / 8, 256>>>(queries, proj, out, on_w, on_b);
}